// round 10
// baseline (speedup 1.0000x reference)
#include <cuda_runtime.h>
#include <cuda_pipeline.h>
#include <math.h>
#include <stdint.h>

#define NDIM     128
#define TROWS    60
#define NWARPS   4
#define RPW      15      // rows per warp
#define NTHREADS 128
#define FULLMASK 0xFFFFFFFFu

// LUT layout: c1[0:64) s1[64:128) c2[128:192) s2[192:256) c3[256:320) s3[320:384)
struct LutParams { float v[384]; };

// Degree-15 odd minimax atan on [0,1] + octant fixup; abs err ~1e-6.
__device__ __forceinline__ float fast_atan2f(float y, float x) {
    float ax = fabsf(x), ay = fabsf(y);
    float mx = fmaxf(ax, ay), mn = fminf(ax, ay);
    float t  = __fdividef(mn, mx);
    float t2 = t * t;
    float p  = -0.0040540580f;
    p = fmaf(p, t2,  0.0218612288f);
    p = fmaf(p, t2, -0.0559098861f);
    p = fmaf(p, t2,  0.0964200441f);
    p = fmaf(p, t2, -0.1390853351f);
    p = fmaf(p, t2,  0.1994653599f);
    p = fmaf(p, t2, -0.3332985605f);
    p = fmaf(p, t2,  0.9999993329f);
    float a = p * t;
    if (ay > ax)   a = 1.57079632679489662f - a;
    if (x < 0.0f)  a = 3.14159265358979323f - a;
    return copysignf(a, y);
}

// branchless fast sqrt: h * rsqrt(max(h, tiny)); h==0 -> 0 * finite = 0
__device__ __forceinline__ float fast_sqrtf(float h) {
    return h * rsqrtf(fmaxf(h, 1e-38f));
}

__global__ __launch_bounds__(NTHREADS, 7)
void nautilus_main(const float* __restrict__ x, float* __restrict__ out,
                   const LutParams lp) {
    __shared__ float s_tile[TROWS * NDIM];   // 30720 B; slots are THREAD-PRIVATE
    __shared__ float s_rmin[NDIM];           // 512 B fold buffer
    __shared__ float s_rmax[NDIM];           // 512 B

    const int tid = threadIdx.x;
    const int w   = tid >> 5;
    const int l   = tid & 31;
    const size_t base = (size_t)blockIdx.x * (size_t)(TROWS * NDIM);

    // ---- front-batch all 15 row-slice copies gmem->smem (MLP=15, no regs) ----
    #pragma unroll
    for (int i = 0; i < RPW; i++) {
        const int off = (w + 4 * i) * NDIM + 4 * l;
        __pipeline_memcpy_async(&s_tile[off], x + base + off, 16);
        __pipeline_commit();
    }

    // ---- per-thread rotation constants straight from constant bank (setup-only) ----
    float c1a = lp.v[2 * l],       s1a = lp.v[64 + 2 * l];
    float c1b = lp.v[2 * l + 1],   s1b = lp.v[64 + 2 * l + 1];
    float cwi = lp.v[128 + 2 * l], swi = lp.v[192 + 2 * l];        // L2 within: k=2l
    // L2 cross coefficients; edge lanes get identity so no predication is needed
    float crr = (l < 31) ? lp.v[128 + 2 * l + 1] : 1.0f;
    float srr = (l < 31) ? lp.v[192 + 2 * l + 1] : 0.0f;
    float cll = (l > 0)  ? lp.v[128 + 2 * l - 1] : 1.0f;
    float sll = (l > 0)  ? lp.v[192 + 2 * l - 1] : 0.0f;
    const bool iside = ((l & 8) == 0);
    int ilane = l & ~8;                                             // i-side lane of xor-8 pair
    float c3v[4], s3v[4];
    #pragma unroll
    for (int q = 0; q < 4; q++) {
        int e = 4 * ilane + q;                 // i-side element index
        int m = (e >= 64) ? (e - 32) : e;      // LUT slot
        c3v[q] = lp.v[256 + m];
        float s3 = lp.v[320 + m];
        s3v[q] = iside ? -s3 : s3;             // i-side: v*c - p*s ; j-side: v*c + p*s
    }

    float mn0 =  INFINITY, mn1 =  INFINITY, mn2 =  INFINITY, mn3 =  INFINITY;
    float mx0 = -INFINITY, mx1 = -INFINITY, mx2 = -INFINITY, mx3 = -INFINITY;

    // ---- pass 1: rotate, polar, min/max; polar overwrites raw x in place ----
    #pragma unroll
    for (int i = 0; i < RPW; i++) {
        __pipeline_wait_prior(RPW - 1 - i);     // row i's slice has landed
        const int off = (w + 4 * i) * NDIM + 4 * l;
        float4 v = *(const float4*)&s_tile[off];
        float v0 = v.x, v1 = v.y, v2 = v.z, v3 = v.w;
        float a, b;

        // layer 1: (2k, 2k+1)
        a = v0; b = v1; v0 = a * c1a - b * s1a; v1 = a * s1a + b * c1a;
        a = v2; b = v3; v2 = a * c1b - b * s1b; v3 = a * s1b + b * c1b;

        // layer 2 within-thread: (4l+1, 4l+2), k=2l
        a = v1; b = v2; v1 = a * cwi - b * swi; v2 = a * swi + b * cwi;

        // layer 2 cross-thread: (4l+3, 4l+4), k=2l+1 — branchless (edge coeffs = identity)
        float nb = __shfl_down_sync(FULLMASK, v0, 1);
        float na = __shfl_up_sync(FULLMASK, v3, 1);
        v3 = v3 * crr - nb * srr;
        v0 = na * sll + v0 * cll;

        // layer 3: (k, k+32) via shfl.xor 8, branch-free (sign folded into s3v)
        float p0 = __shfl_xor_sync(FULLMASK, v0, 8);
        float p1 = __shfl_xor_sync(FULLMASK, v1, 8);
        float p2 = __shfl_xor_sync(FULLMASK, v2, 8);
        float p3 = __shfl_xor_sync(FULLMASK, v3, 8);
        v0 = fmaf(p0, s3v[0], v0 * c3v[0]);
        v1 = fmaf(p1, s3v[1], v1 * c3v[1]);
        v2 = fmaf(p2, s3v[2], v2 * c3v[2]);
        v3 = fmaf(p3, s3v[3], v3 * c3v[3]);

        // polar: (even, odd) pairs are intra-thread
        float h0  = fmaf(v0, v0, v1 * v1);
        float h1  = fmaf(v2, v2, v3 * v3);
        float r0  = fast_sqrtf(h0);
        float r1  = fast_sqrtf(h1);
        float th0 = fast_atan2f(v1, v0);
        float th1 = fast_atan2f(v3, v2);

        mn0 = fminf(mn0, r0);  mx0 = fmaxf(mx0, r0);
        mn1 = fminf(mn1, th0); mx1 = fmaxf(mx1, th0);
        mn2 = fminf(mn2, r1);  mx2 = fmaxf(mx2, r1);
        mn3 = fminf(mn3, th1); mx3 = fmaxf(mx3, th1);

        *(float4*)&s_tile[off] = make_float4(r0, th0, r1, th1);
    }

    // ---- serial warp fold into 1KB buffer (order-independent: exact min/max) ----
    if (w == 0) {
        *(float4*)&s_rmin[4 * l] = make_float4(mn0, mn1, mn2, mn3);
        *(float4*)&s_rmax[4 * l] = make_float4(mx0, mx1, mx2, mx3);
    }
    __syncthreads();
    #pragma unroll
    for (int ww = 1; ww < NWARPS; ww++) {
        if (w == ww) {
            float4 m = *(const float4*)&s_rmin[4 * l];
            float4 X = *(const float4*)&s_rmax[4 * l];
            m.x = fminf(m.x, mn0); m.y = fminf(m.y, mn1);
            m.z = fminf(m.z, mn2); m.w = fminf(m.w, mn3);
            X.x = fmaxf(X.x, mx0); X.y = fmaxf(X.y, mx1);
            X.z = fmaxf(X.z, mx2); X.w = fmaxf(X.w, mx3);
            *(float4*)&s_rmin[4 * l] = m;
            *(float4*)&s_rmax[4 * l] = X;
        }
        __syncthreads();
    }
    float4 rm = *(const float4*)&s_rmin[4 * l];
    float4 rx = *(const float4*)&s_rmax[4 * l];
    float cmnv[4] = {rm.x, rm.y, rm.z, rm.w};
    float cmxv[4] = {rx.x, rx.y, rx.z, rx.w};

    // per-thread quantization constants (4 IEEE divs per thread)
    float scale7[4], nm7[4], q14[4], halfmn[4];
    #pragma unroll
    for (int q = 0; q < 4; q++) {
        float cmn = cmnv[q];
        float crg = fmaxf(cmxv[q] - cmn, 1e-8f);
        scale7[q] = 7.0f / crg;            // (p-mn)*scale7 == norm*7
        nm7[q]    = -cmn * scale7[q];      // norm7 = fma(p, scale7, nm7)
        q14[q]    = crg / 14.0f;           // 0.5 * (crg/7)
        halfmn[q] = 0.5f * cmn;
    }

    // ---- pass 2: quantize + residual correction, write out ----
    // corrected = dq + 0.5*(p-dq) = fma(qv, crg/14, fma(0.5, p, 0.5*mn))
    float* op = out + base;
    #pragma unroll
    for (int i = 0; i < RPW; i++) {
        const int off = (w + 4 * i) * NDIM + 4 * l;
        float4 p = *(const float4*)&s_tile[off];
        float pv[4] = {p.x, p.y, p.z, p.w};
        float res[4];
        #pragma unroll
        for (int q = 0; q < 4; q++) {
            float norm7 = fmaf(pv[q], scale7[q], nm7[q]);  // in [0,7] by construction
            float qv    = rintf(norm7);                    // half-to-even
            res[q] = fmaf(qv, q14[q], fmaf(0.5f, pv[q], halfmn[q]));
        }
        *(float4*)(op + (size_t)off) = make_float4(res[0], res[1], res[2], res[3]);
    }
}

static void build_lut_host(LutParams* p) {
    const double PHI = 1.6180339887498948482045868343656;
    const double GA  = 6.2831853071795864769252867665590 / (PHI * PHI);
    for (int k = 0; k < 64; k++) {
        double a1 = GA * (double)(k + 1);
        p->v[k]        = (float)cos(a1);
        p->v[64 + k]   = (float)sin(a1);
        if (k < 63) {
            double a2 = GA * (double)(k + 1) * PHI;
            p->v[128 + k] = (float)cos(a2);
            p->v[192 + k] = (float)sin(a2);
        } else {
            p->v[128 + k] = 0.0f;
            p->v[192 + k] = 0.0f;
        }
        int kk = (k < 32) ? k : (k + 32);   // layer3 accepted ks: 0..31, 64..95
        double a3 = GA * (double)(kk + 1) * PHI * PHI;
        p->v[256 + k] = (float)cos(a3);
        p->v[320 + k] = (float)sin(a3);
    }
}

extern "C" void kernel_launch(void* const* d_in, const int* in_sizes, int n_in,
                              void* d_out, int out_size) {
    const float* x = (const float*)d_in[0];
    float* out = (float*)d_out;
    int nrows  = in_sizes[0] / NDIM;
    int ntiles = nrows / TROWS;
    LutParams lp;
    build_lut_host(&lp);                 // host-side, no device work
    nautilus_main<<<ntiles, NTHREADS>>>(x, out, lp);
}

// round 11
// speedup vs baseline: 1.1994x; 1.1994x over previous
#include <cuda_runtime.h>
#include <cuda_pipeline.h>
#include <math.h>
#include <stdint.h>

#define NDIM     128
#define TROWS    60
#define NWARPS   4
#define RPW      15      // rows per warp
#define NTHREADS 128
#define FULLMASK 0xFFFFFFFFu

typedef unsigned long long u64;

// ---- Blackwell packed f32x2 helpers (SASS FFMA2/FMUL2; PTX-only) ----
__device__ __forceinline__ u64 pk2(float lo, float hi) {
    u64 r; asm("mov.b64 %0, {%1, %2};" : "=l"(r) : "f"(lo), "f"(hi)); return r;
}
__device__ __forceinline__ void upk2(u64 v, float& lo, float& hi) {
    asm("mov.b64 {%0, %1}, %2;" : "=f"(lo), "=f"(hi) : "l"(v));
}
__device__ __forceinline__ u64 fma2(u64 a, u64 b, u64 c) {
    u64 d; asm("fma.rn.f32x2 %0, %1, %2, %3;" : "=l"(d) : "l"(a), "l"(b), "l"(c)); return d;
}
__device__ __forceinline__ u64 mul2(u64 a, u64 b) {
    u64 d; asm("mul.rn.f32x2 %0, %1, %2;" : "=l"(d) : "l"(a), "l"(b)); return d;
}

// LUT layout: c1[0:64) s1[64:128) c2[128:192) s2[192:256) c3[256:320) s3[320:384)
struct LutParams { float v[384]; };

// Degree-15 odd minimax atan on [0,1] + octant fixup; abs err ~1e-6.
__device__ __forceinline__ float fast_atan2f(float y, float x) {
    float ax = fabsf(x), ay = fabsf(y);
    float mx = fmaxf(ax, ay), mn = fminf(ax, ay);
    float t  = __fdividef(mn, mx);
    float t2 = t * t;
    float p  = -0.0040540580f;
    p = fmaf(p, t2,  0.0218612288f);
    p = fmaf(p, t2, -0.0559098861f);
    p = fmaf(p, t2,  0.0964200441f);
    p = fmaf(p, t2, -0.1390853351f);
    p = fmaf(p, t2,  0.1994653599f);
    p = fmaf(p, t2, -0.3332985605f);
    p = fmaf(p, t2,  0.9999993329f);
    float a = p * t;
    if (ay > ax)   a = 1.57079632679489662f - a;
    if (x < 0.0f)  a = 3.14159265358979323f - a;
    return copysignf(a, y);
}

// branchless fast sqrt: h * rsqrt(max(h, tiny)); h==0 -> 0 * finite = 0
__device__ __forceinline__ float fast_sqrtf(float h) {
    return h * rsqrtf(fmaxf(h, 1e-38f));
}

__global__ __launch_bounds__(NTHREADS, 6)
void nautilus_main(const float* __restrict__ x, float* __restrict__ out,
                   const LutParams lp) {
    __shared__ float s_lut[384];
    __shared__ float s_tile[TROWS * NDIM];       // 30720 B; slots are THREAD-PRIVATE
    __shared__ float s_pmin[NWARPS][NDIM];       // per-warp partial min
    __shared__ float s_pmax[NWARPS][NDIM];

    const int tid = threadIdx.x;
    const int w   = tid >> 5;
    const int l   = tid & 31;
    const size_t base = (size_t)blockIdx.x * (size_t)(TROWS * NDIM);

    // ---- front-batch all 15 row-slice copies gmem->smem (MLP=15, no regs) ----
    #pragma unroll
    for (int i = 0; i < RPW; i++) {
        const int off = (w + 4 * i) * NDIM + 4 * l;
        __pipeline_memcpy_async(&s_tile[off], x + base + off, 16);
        __pipeline_commit();
    }

    // stage LUT param -> smem (uniform LDC, overlaps with cp.async flight)
    #pragma unroll
    for (int i = tid; i < 384; i += NTHREADS) s_lut[i] = lp.v[i];
    __syncthreads();

    // ---- per-thread rotation constants, packed for f32x2 ----
    // layer 1: lane pair (v0,v2) rotates with (c1a,c1b)
    u64 C1  = pk2(s_lut[2 * l],        s_lut[2 * l + 1]);
    u64 S1  = pk2(s_lut[64 + 2 * l],   s_lut[64 + 2 * l + 1]);
    u64 nS1 = pk2(-s_lut[64 + 2 * l], -s_lut[64 + 2 * l + 1]);
    float cwi = s_lut[128 + 2 * l], swi = s_lut[192 + 2 * l];      // L2 within: k=2l
    // L2 cross coefficients; edge lanes get identity (no predication)
    float crr = (l < 31) ? s_lut[128 + 2 * l + 1] : 1.0f;
    float srr = (l < 31) ? s_lut[192 + 2 * l + 1] : 0.0f;
    float cll = (l > 0)  ? s_lut[128 + 2 * l - 1] : 1.0f;
    float sll = (l > 0)  ? s_lut[192 + 2 * l - 1] : 0.0f;
    const bool iside = ((l & 8) == 0);
    int ilane = l & ~8;                                             // i-side lane of xor-8 pair
    float c3s[4], s3s[4];
    #pragma unroll
    for (int q = 0; q < 4; q++) {
        int e = 4 * ilane + q;                 // i-side element index
        int m = (e >= 64) ? (e - 32) : e;      // LUT slot
        c3s[q] = s_lut[256 + m];
        float s3 = s_lut[320 + m];
        s3s[q] = iside ? -s3 : s3;             // i-side: v*c - p*s ; j-side: v*c + p*s
    }
    u64 C3_02 = pk2(c3s[0], c3s[2]), C3_13 = pk2(c3s[1], c3s[3]);
    u64 S3_02 = pk2(s3s[0], s3s[2]), S3_13 = pk2(s3s[1], s3s[3]);

    float mn0 =  INFINITY, mn1 =  INFINITY, mn2 =  INFINITY, mn3 =  INFINITY;
    float mx0 = -INFINITY, mx1 = -INFINITY, mx2 = -INFINITY, mx3 = -INFINITY;

    // ---- pass 1: rotate, polar, min/max; polar overwrites raw x in place ----
    #pragma unroll
    for (int i = 0; i < RPW; i++) {
        __pipeline_wait_prior(RPW - 1 - i);     // row i's slice has landed
        const int off = (w + 4 * i) * NDIM + 4 * l;
        float4 v = *(const float4*)&s_tile[off];

        // layer 1 (packed): A=(v0,v2), B=(v1,v3); A'=A*C1-B*S1, B'=A*S1+B*C1
        u64 A = pk2(v.x, v.z);
        u64 B = pk2(v.y, v.w);
        u64 A1 = fma2(B, nS1, mul2(A, C1));
        u64 B1 = fma2(A, S1,  mul2(B, C1));
        float v0, v1, v2, v3;
        upk2(A1, v0, v2);
        upk2(B1, v1, v3);

        // layer 2 within-thread: (4l+1, 4l+2), k=2l — scalar (cross-half)
        float a = v1, b = v2;
        v1 = a * cwi - b * swi; v2 = a * swi + b * cwi;

        // layer 2 cross-thread: (4l+3, 4l+4), k=2l+1 — branchless
        float nb = __shfl_down_sync(FULLMASK, v0, 1);
        float na = __shfl_up_sync(FULLMASK, v3, 1);
        v3 = v3 * crr - nb * srr;
        v0 = na * sll + v0 * cll;

        // layer 3 (packed): v' = p*s3 + v*c3, sign folded into s3
        float p0 = __shfl_xor_sync(FULLMASK, v0, 8);
        float p1 = __shfl_xor_sync(FULLMASK, v1, 8);
        float p2 = __shfl_xor_sync(FULLMASK, v2, 8);
        float p3 = __shfl_xor_sync(FULLMASK, v3, 8);
        u64 V02 = pk2(v0, v2), V13 = pk2(v1, v3);
        u64 P02 = pk2(p0, p2), P13 = pk2(p1, p3);
        V02 = fma2(P02, S3_02, mul2(V02, C3_02));
        V13 = fma2(P13, S3_13, mul2(V13, C3_13));

        // polar magnitude (packed): H = V13^2 + V02^2 = (h0, h1)
        u64 H = fma2(V13, V13, mul2(V02, V02));
        float h0, h1;
        upk2(H, h0, h1);
        upk2(V02, v0, v2);
        upk2(V13, v1, v3);
        float r0  = fast_sqrtf(h0);
        float r1  = fast_sqrtf(h1);
        float th0 = fast_atan2f(v1, v0);
        float th1 = fast_atan2f(v3, v2);

        mn0 = fminf(mn0, r0);  mx0 = fmaxf(mx0, r0);
        mn1 = fminf(mn1, th0); mx1 = fmaxf(mx1, th0);
        mn2 = fminf(mn2, r1);  mx2 = fmaxf(mx2, r1);
        mn3 = fminf(mn3, th1); mx3 = fmaxf(mx3, th1);

        *(float4*)&s_tile[off] = make_float4(r0, th0, r1, th1);
    }

    *(float4*)&s_pmin[w][4 * l] = make_float4(mn0, mn1, mn2, mn3);
    *(float4*)&s_pmax[w][4 * l] = make_float4(mx0, mx1, mx2, mx3);
    __syncthreads();

    // single-barrier reduction: every thread combines the 4 warp partials
    float4 a0 = *(const float4*)&s_pmin[0][4 * l];
    float4 a1 = *(const float4*)&s_pmin[1][4 * l];
    float4 a2 = *(const float4*)&s_pmin[2][4 * l];
    float4 a3 = *(const float4*)&s_pmin[3][4 * l];
    float4 b0 = *(const float4*)&s_pmax[0][4 * l];
    float4 b1 = *(const float4*)&s_pmax[1][4 * l];
    float4 b2 = *(const float4*)&s_pmax[2][4 * l];
    float4 b3 = *(const float4*)&s_pmax[3][4 * l];
    float cmnv[4], cmxv[4];
    cmnv[0] = fminf(fminf(a0.x, a1.x), fminf(a2.x, a3.x));
    cmnv[1] = fminf(fminf(a0.y, a1.y), fminf(a2.y, a3.y));
    cmnv[2] = fminf(fminf(a0.z, a1.z), fminf(a2.z, a3.z));
    cmnv[3] = fminf(fminf(a0.w, a1.w), fminf(a2.w, a3.w));
    cmxv[0] = fmaxf(fmaxf(b0.x, b1.x), fmaxf(b2.x, b3.x));
    cmxv[1] = fmaxf(fmaxf(b0.y, b1.y), fmaxf(b2.y, b3.y));
    cmxv[2] = fmaxf(fmaxf(b0.z, b1.z), fmaxf(b2.z, b3.z));
    cmxv[3] = fmaxf(fmaxf(b0.w, b1.w), fmaxf(b2.w, b3.w));

    // packed per-thread quantization constants (4 IEEE divs per thread)
    float sc[4], nm[4], qq[4], hm[4];
    #pragma unroll
    for (int q = 0; q < 4; q++) {
        float cmn = cmnv[q];
        float crg = fmaxf(cmxv[q] - cmn, 1e-8f);
        sc[q] = 7.0f / crg;            // (p-mn)*sc == norm*7
        nm[q] = -cmn * sc[q];          // norm7 = fma(p, sc, nm)
        qq[q] = crg / 14.0f;           // 0.5 * (crg/7)
        hm[q] = 0.5f * cmn;
    }
    u64 SC02 = pk2(sc[0], sc[2]), SC13 = pk2(sc[1], sc[3]);
    u64 NM02 = pk2(nm[0], nm[2]), NM13 = pk2(nm[1], nm[3]);
    u64 QQ02 = pk2(qq[0], qq[2]), QQ13 = pk2(qq[1], qq[3]);
    u64 HM02 = pk2(hm[0], hm[2]), HM13 = pk2(hm[1], hm[3]);
    u64 HALF = pk2(0.5f, 0.5f);

    // ---- pass 2: quantize + residual correction (packed), write out ----
    // corrected = fma(qv, crg/14, fma(0.5, p, 0.5*mn))
    float* op = out + base;
    #pragma unroll
    for (int i = 0; i < RPW; i++) {
        const int off = (w + 4 * i) * NDIM + 4 * l;
        float4 p = *(const float4*)&s_tile[off];
        u64 P02 = pk2(p.x, p.z), P13 = pk2(p.y, p.w);
        u64 N02 = fma2(P02, SC02, NM02);
        u64 N13 = fma2(P13, SC13, NM13);
        float n0, n1, n2, n3;
        upk2(N02, n0, n2);
        upk2(N13, n1, n3);
        u64 QV02 = pk2(rintf(n0), rintf(n2));   // half-to-even, in [0,7]
        u64 QV13 = pk2(rintf(n1), rintf(n3));
        u64 R02 = fma2(QV02, QQ02, fma2(HALF, P02, HM02));
        u64 R13 = fma2(QV13, QQ13, fma2(HALF, P13, HM13));
        float r0, r1, r2, r3;
        upk2(R02, r0, r2);
        upk2(R13, r1, r3);
        *(float4*)(op + (size_t)off) = make_float4(r0, r1, r2, r3);
    }
}

static void build_lut_host(LutParams* p) {
    const double PHI = 1.6180339887498948482045868343656;
    const double GA  = 6.2831853071795864769252867665590 / (PHI * PHI);
    for (int k = 0; k < 64; k++) {
        double a1 = GA * (double)(k + 1);
        p->v[k]        = (float)cos(a1);
        p->v[64 + k]   = (float)sin(a1);
        if (k < 63) {
            double a2 = GA * (double)(k + 1) * PHI;
            p->v[128 + k] = (float)cos(a2);
            p->v[192 + k] = (float)sin(a2);
        } else {
            p->v[128 + k] = 0.0f;
            p->v[192 + k] = 0.0f;
        }
        int kk = (k < 32) ? k : (k + 32);   // layer3 accepted ks: 0..31, 64..95
        double a3 = GA * (double)(kk + 1) * PHI * PHI;
        p->v[256 + k] = (float)cos(a3);
        p->v[320 + k] = (float)sin(a3);
    }
}

extern "C" void kernel_launch(void* const* d_in, const int* in_sizes, int n_in,
                              void* d_out, int out_size) {
    const float* x = (const float*)d_in[0];
    float* out = (float*)d_out;
    int nrows  = in_sizes[0] / NDIM;
    int ntiles = nrows / TROWS;
    LutParams lp;
    build_lut_host(&lp);                 // host-side, no device work
    nautilus_main<<<ntiles, NTHREADS>>>(x, out, lp);
}

// round 14
// speedup vs baseline: 1.2502x; 1.0423x over previous
#include <cuda_runtime.h>
#include <cuda_pipeline.h>
#include <math.h>
#include <stdint.h>

#define NDIM     128
#define TROWS    60
#define NWARPS   4
#define RPW      15      // rows per warp
#define NTHREADS 128
#define FULLMASK 0xFFFFFFFFu

// LUT layout: c1[0:64) s1[64:128) c2[128:192) s2[192:256) c3[256:320) s3[320:384)
struct LutParams { float v[384]; };

// Degree-15 odd minimax atan on [0,1] + octant fixup; abs err ~1e-6.
// Estrin evaluation: same coefficients as Horner, ~12 cycles shorter critical path.
__device__ __forceinline__ float fast_atan2f(float y, float x) {
    float ax = fabsf(x), ay = fabsf(y);
    float mx = fmaxf(ax, ay), mn = fminf(ax, ay);
    float t  = __fdividef(mn, mx);
    float u  = t * t;
    float u2 = u * u;
    float u4 = u2 * u2;
    // p(u) = c0 + c1 u + ... + c7 u^7   (c0 = 0.9999993329 ... c7 = -0.0040540580)
    float q0 = fmaf(u, -0.3332985605f,  0.9999993329f);
    float q1 = fmaf(u, -0.1390853351f,  0.1994653599f);
    float q2 = fmaf(u, -0.0559098861f,  0.0964200441f);
    float q3 = fmaf(u, -0.0040540580f,  0.0218612288f);
    float r0 = fmaf(q1, u2, q0);
    float r1 = fmaf(q3, u2, q2);
    float p  = fmaf(r1, u4, r0);
    float a  = p * t;
    if (ay > ax)   a = 1.57079632679489662f - a;
    if (x < 0.0f)  a = 3.14159265358979323f - a;
    return copysignf(a, y);
}

// branchless fast sqrt: h * rsqrt(max(h, tiny)); h==0 -> 0 * finite = 0
__device__ __forceinline__ float fast_sqrtf(float h) {
    return h * rsqrtf(fmaxf(h, 1e-38f));
}

__global__ __launch_bounds__(NTHREADS, 6)
void nautilus_main(const float* __restrict__ x, float* __restrict__ out,
                   const LutParams lp) {
    __shared__ float s_lut[384];
    __shared__ float s_tile[TROWS * NDIM];       // 30720 B; slots are THREAD-PRIVATE
    __shared__ float s_pmin[NWARPS][NDIM];       // per-warp partial min
    __shared__ float s_pmax[NWARPS][NDIM];

    const int tid = threadIdx.x;
    const int w   = tid >> 5;
    const int l   = tid & 31;
    const size_t base = (size_t)blockIdx.x * (size_t)(TROWS * NDIM);

    // ---- front-batch all 15 row-slice copies gmem->smem (MLP=15, no regs) ----
    #pragma unroll
    for (int i = 0; i < RPW; i++) {
        const int off = (w + 4 * i) * NDIM + 4 * l;
        __pipeline_memcpy_async(&s_tile[off], x + base + off, 16);
        __pipeline_commit();
    }

    // stage LUT param -> smem (uniform LDC; overlaps with cp.async flight)
    #pragma unroll
    for (int i = tid; i < 384; i += NTHREADS) s_lut[i] = lp.v[i];
    __syncthreads();

    // ---- per-thread rotation constants (uniform across rows) ----
    float c1a = s_lut[2 * l],       s1a = s_lut[64 + 2 * l];
    float c1b = s_lut[2 * l + 1],   s1b = s_lut[64 + 2 * l + 1];
    float cwi = s_lut[128 + 2 * l], swi = s_lut[192 + 2 * l];      // L2 within: k=2l
    // L2 cross coefficients; edge lanes get identity so no predication is needed
    float crr = (l < 31) ? s_lut[128 + 2 * l + 1] : 1.0f;
    float srr = (l < 31) ? s_lut[192 + 2 * l + 1] : 0.0f;
    float cll = (l > 0)  ? s_lut[128 + 2 * l - 1] : 1.0f;
    float sll = (l > 0)  ? s_lut[192 + 2 * l - 1] : 0.0f;
    const bool iside = ((l & 8) == 0);
    int ilane = l & ~8;                                             // i-side lane of xor-8 pair
    float c3v[4], s3v[4];
    #pragma unroll
    for (int q = 0; q < 4; q++) {
        int e = 4 * ilane + q;                 // i-side element index
        int m = (e >= 64) ? (e - 32) : e;      // LUT slot
        c3v[q] = s_lut[256 + m];
        float s3 = s_lut[320 + m];
        s3v[q] = iside ? -s3 : s3;             // i-side: v*c - p*s ; j-side: v*c + p*s
    }

    float mn0 =  INFINITY, mn1 =  INFINITY, mn2 =  INFINITY, mn3 =  INFINITY;
    float mx0 = -INFINITY, mx1 = -INFINITY, mx2 = -INFINITY, mx3 = -INFINITY;

    // ---- pass 1: rotate, polar, min/max; polar overwrites raw x in place ----
    #pragma unroll
    for (int i = 0; i < RPW; i++) {
        __pipeline_wait_prior(RPW - 1 - i);     // row i's slice has landed
        const int off = (w + 4 * i) * NDIM + 4 * l;
        float4 v = *(const float4*)&s_tile[off];
        float v0 = v.x, v1 = v.y, v2 = v.z, v3 = v.w;
        float a, b;

        // layer 1: (2k, 2k+1)
        a = v0; b = v1; v0 = a * c1a - b * s1a; v1 = a * s1a + b * c1a;
        a = v2; b = v3; v2 = a * c1b - b * s1b; v3 = a * s1b + b * c1b;

        // layer 2 within-thread: (4l+1, 4l+2), k=2l
        a = v1; b = v2; v1 = a * cwi - b * swi; v2 = a * swi + b * cwi;

        // layer 2 cross-thread: (4l+3, 4l+4), k=2l+1 — branchless (edge coeffs = identity)
        float nb = __shfl_down_sync(FULLMASK, v0, 1);
        float na = __shfl_up_sync(FULLMASK, v3, 1);
        v3 = v3 * crr - nb * srr;
        v0 = na * sll + v0 * cll;

        // layer 3: (k, k+32) via shfl.xor 8, branch-free (sign folded into s3v)
        float p0 = __shfl_xor_sync(FULLMASK, v0, 8);
        float p1 = __shfl_xor_sync(FULLMASK, v1, 8);
        float p2 = __shfl_xor_sync(FULLMASK, v2, 8);
        float p3 = __shfl_xor_sync(FULLMASK, v3, 8);
        v0 = fmaf(p0, s3v[0], v0 * c3v[0]);
        v1 = fmaf(p1, s3v[1], v1 * c3v[1]);
        v2 = fmaf(p2, s3v[2], v2 * c3v[2]);
        v3 = fmaf(p3, s3v[3], v3 * c3v[3]);

        // polar: (even, odd) pairs are intra-thread; two independent chains
        float h0  = fmaf(v0, v0, v1 * v1);
        float h1  = fmaf(v2, v2, v3 * v3);
        float r0  = fast_sqrtf(h0);
        float r1  = fast_sqrtf(h1);
        float th0 = fast_atan2f(v1, v0);
        float th1 = fast_atan2f(v3, v2);

        mn0 = fminf(mn0, r0);  mx0 = fmaxf(mx0, r0);
        mn1 = fminf(mn1, th0); mx1 = fmaxf(mx1, th0);
        mn2 = fminf(mn2, r1);  mx2 = fmaxf(mx2, r1);
        mn3 = fminf(mn3, th1); mx3 = fmaxf(mx3, th1);

        *(float4*)&s_tile[off] = make_float4(r0, th0, r1, th1);
    }

    *(float4*)&s_pmin[w][4 * l] = make_float4(mn0, mn1, mn2, mn3);
    *(float4*)&s_pmax[w][4 * l] = make_float4(mx0, mx1, mx2, mx3);
    __syncthreads();

    // single-barrier reduction: every thread combines the 4 warp partials
    float4 a0 = *(const float4*)&s_pmin[0][4 * l];
    float4 a1 = *(const float4*)&s_pmin[1][4 * l];
    float4 a2 = *(const float4*)&s_pmin[2][4 * l];
    float4 a3 = *(const float4*)&s_pmin[3][4 * l];
    float4 b0 = *(const float4*)&s_pmax[0][4 * l];
    float4 b1 = *(const float4*)&s_pmax[1][4 * l];
    float4 b2 = *(const float4*)&s_pmax[2][4 * l];
    float4 b3 = *(const float4*)&s_pmax[3][4 * l];
    float cmnv[4], cmxv[4];
    cmnv[0] = fminf(fminf(a0.x, a1.x), fminf(a2.x, a3.x));
    cmnv[1] = fminf(fminf(a0.y, a1.y), fminf(a2.y, a3.y));
    cmnv[2] = fminf(fminf(a0.z, a1.z), fminf(a2.z, a3.z));
    cmnv[3] = fminf(fminf(a0.w, a1.w), fminf(a2.w, a3.w));
    cmxv[0] = fmaxf(fmaxf(b0.x, b1.x), fmaxf(b2.x, b3.x));
    cmxv[1] = fmaxf(fmaxf(b0.y, b1.y), fmaxf(b2.y, b3.y));
    cmxv[2] = fmaxf(fmaxf(b0.z, b1.z), fmaxf(b2.z, b3.z));
    cmxv[3] = fmaxf(fmaxf(b0.w, b1.w), fmaxf(b2.w, b3.w));

    // per-thread quantization constants (4 IEEE divs per thread)
    float scale7[4], nm7[4], q14[4], halfmn[4];
    #pragma unroll
    for (int q = 0; q < 4; q++) {
        float cmn = cmnv[q];
        float crg = fmaxf(cmxv[q] - cmn, 1e-8f);
        scale7[q] = 7.0f / crg;            // (p-mn)*scale7 == norm*7
        nm7[q]    = -cmn * scale7[q];      // norm7 = fma(p, scale7, nm7)
        q14[q]    = crg / 14.0f;           // 0.5 * (crg/7)
        halfmn[q] = 0.5f * cmn;
    }

    // ---- pass 2: quantize + residual correction; streaming stores ----
    // corrected = dq + 0.5*(p-dq) = fma(qv, crg/14, fma(0.5, p, 0.5*mn))
    float* op = out + base;
    #pragma unroll
    for (int i = 0; i < RPW; i++) {
        const int off = (w + 4 * i) * NDIM + 4 * l;
        float4 p = *(const float4*)&s_tile[off];
        float pv[4] = {p.x, p.y, p.z, p.w};
        float res[4];
        #pragma unroll
        for (int q = 0; q < 4; q++) {
            float norm7 = fmaf(pv[q], scale7[q], nm7[q]);  // in [0,7] by construction
            float qv    = rintf(norm7);                    // half-to-even
            res[q] = fmaf(qv, q14[q], fmaf(0.5f, pv[q], halfmn[q]));
        }
        __stcs((float4*)(op + (size_t)off), make_float4(res[0], res[1], res[2], res[3]));
    }
}

static void build_lut_host(LutParams* p) {
    const double PHI = 1.6180339887498948482045868343656;
    const double GA  = 6.2831853071795864769252867665590 / (PHI * PHI);
    for (int k = 0; k < 64; k++) {
        double a1 = GA * (double)(k + 1);
        p->v[k]        = (float)cos(a1);
        p->v[64 + k]   = (float)sin(a1);
        if (k < 63) {
            double a2 = GA * (double)(k + 1) * PHI;
            p->v[128 + k] = (float)cos(a2);
            p->v[192 + k] = (float)sin(a2);
        } else {
            p->v[128 + k] = 0.0f;
            p->v[192 + k] = 0.0f;
        }
        int kk = (k < 32) ? k : (k + 32);   // layer3 accepted ks: 0..31, 64..95
        double a3 = GA * (double)(kk + 1) * PHI * PHI;
        p->v[256 + k] = (float)cos(a3);
        p->v[320 + k] = (float)sin(a3);
    }
}

extern "C" void kernel_launch(void* const* d_in, const int* in_sizes, int n_in,
                              void* d_out, int out_size) {
    const float* x = (const float*)d_in[0];
    float* out = (float*)d_out;
    int nrows  = in_sizes[0] / NDIM;
    int ntiles = nrows / TROWS;
    LutParams lp;
    build_lut_host(&lp);                 // host-side, no device work
    nautilus_main<<<ntiles, NTHREADS>>>(x, out, lp);
}

// round 15
// speedup vs baseline: 1.3037x; 1.0428x over previous
#include <cuda_runtime.h>
#include <cuda_pipeline.h>
#include <math.h>
#include <stdint.h>

#define NDIM     128
#define TROWS    60
#define NWARPS   4
#define RPW      15      // rows per warp
#define PDEPTH   8       // cp.async software-pipeline depth
#define NTHREADS 128
#define FULLMASK 0xFFFFFFFFu

// LUT layout: c1[0:64) s1[64:128) c2[128:192) s2[192:256) c3[256:320) s3[320:384)
struct LutParams { float v[384]; };

// Degree-15 odd minimax atan on [0,1] + octant fixup; abs err ~1e-6.
__device__ __forceinline__ float fast_atan2f(float y, float x) {
    float ax = fabsf(x), ay = fabsf(y);
    float mx = fmaxf(ax, ay), mn = fminf(ax, ay);
    float t  = __fdividef(mn, mx);
    float t2 = t * t;
    float p  = -0.0040540580f;
    p = fmaf(p, t2,  0.0218612288f);
    p = fmaf(p, t2, -0.0559098861f);
    p = fmaf(p, t2,  0.0964200441f);
    p = fmaf(p, t2, -0.1390853351f);
    p = fmaf(p, t2,  0.1994653599f);
    p = fmaf(p, t2, -0.3332985605f);
    p = fmaf(p, t2,  0.9999993329f);
    float a = p * t;
    if (ay > ax)   a = 1.57079632679489662f - a;
    if (x < 0.0f)  a = 3.14159265358979323f - a;
    return copysignf(a, y);
}

// branchless fast sqrt: h * rsqrt(max(h, tiny)); h==0 -> 0 * finite = 0
__device__ __forceinline__ float fast_sqrtf(float h) {
    return h * rsqrtf(fmaxf(h, 1e-38f));
}

__global__ __launch_bounds__(NTHREADS, 6)
void nautilus_main(const float* __restrict__ x, float* __restrict__ out,
                   const LutParams lp) {
    __shared__ float s_lut[384];
    __shared__ float s_tile[TROWS * NDIM];       // 30720 B; slots are THREAD-PRIVATE
    __shared__ float s_pmin[NWARPS][NDIM];       // per-warp partial min
    __shared__ float s_pmax[NWARPS][NDIM];

    const int tid = threadIdx.x;
    const int w   = tid >> 5;
    const int l   = tid & 31;
    const size_t base = (size_t)blockIdx.x * (size_t)(TROWS * NDIM);

    // ---- prologue: issue first PDEPTH row-slice copies (bounded MLP) ----
    #pragma unroll
    for (int i = 0; i < PDEPTH; i++) {
        const int off = (w + 4 * i) * NDIM + 4 * l;
        __pipeline_memcpy_async(&s_tile[off], x + base + off, 16);
        __pipeline_commit();
    }

    // stage LUT param -> smem (uniform LDC; overlaps with cp.async flight)
    #pragma unroll
    for (int i = tid; i < 384; i += NTHREADS) s_lut[i] = lp.v[i];
    __syncthreads();

    // ---- per-thread rotation constants (uniform across rows) ----
    float c1a = s_lut[2 * l],       s1a = s_lut[64 + 2 * l];
    float c1b = s_lut[2 * l + 1],   s1b = s_lut[64 + 2 * l + 1];
    float cwi = s_lut[128 + 2 * l], swi = s_lut[192 + 2 * l];      // L2 within: k=2l
    // L2 cross coefficients; edge lanes get identity so no predication is needed
    float crr = (l < 31) ? s_lut[128 + 2 * l + 1] : 1.0f;
    float srr = (l < 31) ? s_lut[192 + 2 * l + 1] : 0.0f;
    float cll = (l > 0)  ? s_lut[128 + 2 * l - 1] : 1.0f;
    float sll = (l > 0)  ? s_lut[192 + 2 * l - 1] : 0.0f;
    const bool iside = ((l & 8) == 0);
    int ilane = l & ~8;                                             // i-side lane of xor-8 pair
    float c3v[4], s3v[4];
    #pragma unroll
    for (int q = 0; q < 4; q++) {
        int e = 4 * ilane + q;                 // i-side element index
        int m = (e >= 64) ? (e - 32) : e;      // LUT slot
        c3v[q] = s_lut[256 + m];
        float s3 = s_lut[320 + m];
        s3v[q] = iside ? -s3 : s3;             // i-side: v*c - p*s ; j-side: v*c + p*s
    }

    float mn0 =  INFINITY, mn1 =  INFINITY, mn2 =  INFINITY, mn3 =  INFINITY;
    float mx0 = -INFINITY, mx1 = -INFINITY, mx2 = -INFINITY, mx3 = -INFINITY;

    // ---- pass 1: depth-8 pipelined; rotate, polar, min/max; overwrite in place ----
    #pragma unroll
    for (int i = 0; i < RPW; i++) {
        // issue row i+PDEPTH's copy before consuming row i (keeps 8 in flight)
        if (i + PDEPTH < RPW) {
            const int foff = (w + 4 * (i + PDEPTH)) * NDIM + 4 * l;
            __pipeline_memcpy_async(&s_tile[foff], x + base + foff, 16);
            __pipeline_commit();
        }
        // row i needs groups 0..i done; pending allowed = min(PDEPTH, RPW-1-i)
        __pipeline_wait_prior((PDEPTH < RPW - 1 - i) ? PDEPTH : (RPW - 1 - i));

        const int off = (w + 4 * i) * NDIM + 4 * l;
        float4 v = *(const float4*)&s_tile[off];
        float v0 = v.x, v1 = v.y, v2 = v.z, v3 = v.w;
        float a, b;

        // layer 1: (2k, 2k+1)
        a = v0; b = v1; v0 = a * c1a - b * s1a; v1 = a * s1a + b * c1a;
        a = v2; b = v3; v2 = a * c1b - b * s1b; v3 = a * s1b + b * c1b;

        // layer 2 within-thread: (4l+1, 4l+2), k=2l
        a = v1; b = v2; v1 = a * cwi - b * swi; v2 = a * swi + b * cwi;

        // layer 2 cross-thread: (4l+3, 4l+4), k=2l+1 — branchless (edge coeffs = identity)
        float nb = __shfl_down_sync(FULLMASK, v0, 1);
        float na = __shfl_up_sync(FULLMASK, v3, 1);
        v3 = v3 * crr - nb * srr;
        v0 = na * sll + v0 * cll;

        // layer 3: (k, k+32) via shfl.xor 8, branch-free (sign folded into s3v)
        float p0 = __shfl_xor_sync(FULLMASK, v0, 8);
        float p1 = __shfl_xor_sync(FULLMASK, v1, 8);
        float p2 = __shfl_xor_sync(FULLMASK, v2, 8);
        float p3 = __shfl_xor_sync(FULLMASK, v3, 8);
        v0 = fmaf(p0, s3v[0], v0 * c3v[0]);
        v1 = fmaf(p1, s3v[1], v1 * c3v[1]);
        v2 = fmaf(p2, s3v[2], v2 * c3v[2]);
        v3 = fmaf(p3, s3v[3], v3 * c3v[3]);

        // polar: (even, odd) pairs are intra-thread
        float h0  = fmaf(v0, v0, v1 * v1);
        float h1  = fmaf(v2, v2, v3 * v3);
        float r0  = fast_sqrtf(h0);
        float r1  = fast_sqrtf(h1);
        float th0 = fast_atan2f(v1, v0);
        float th1 = fast_atan2f(v3, v2);

        mn0 = fminf(mn0, r0);  mx0 = fmaxf(mx0, r0);
        mn1 = fminf(mn1, th0); mx1 = fmaxf(mx1, th0);
        mn2 = fminf(mn2, r1);  mx2 = fmaxf(mx2, r1);
        mn3 = fminf(mn3, th1); mx3 = fmaxf(mx3, th1);

        *(float4*)&s_tile[off] = make_float4(r0, th0, r1, th1);
    }

    *(float4*)&s_pmin[w][4 * l] = make_float4(mn0, mn1, mn2, mn3);
    *(float4*)&s_pmax[w][4 * l] = make_float4(mx0, mx1, mx2, mx3);
    __syncthreads();

    // single-barrier reduction: every thread combines the 4 warp partials
    float4 a0 = *(const float4*)&s_pmin[0][4 * l];
    float4 a1 = *(const float4*)&s_pmin[1][4 * l];
    float4 a2 = *(const float4*)&s_pmin[2][4 * l];
    float4 a3 = *(const float4*)&s_pmin[3][4 * l];
    float4 b0 = *(const float4*)&s_pmax[0][4 * l];
    float4 b1 = *(const float4*)&s_pmax[1][4 * l];
    float4 b2 = *(const float4*)&s_pmax[2][4 * l];
    float4 b3 = *(const float4*)&s_pmax[3][4 * l];
    float cmnv[4], cmxv[4];
    cmnv[0] = fminf(fminf(a0.x, a1.x), fminf(a2.x, a3.x));
    cmnv[1] = fminf(fminf(a0.y, a1.y), fminf(a2.y, a3.y));
    cmnv[2] = fminf(fminf(a0.z, a1.z), fminf(a2.z, a3.z));
    cmnv[3] = fminf(fminf(a0.w, a1.w), fminf(a2.w, a3.w));
    cmxv[0] = fmaxf(fmaxf(b0.x, b1.x), fmaxf(b2.x, b3.x));
    cmxv[1] = fmaxf(fmaxf(b0.y, b1.y), fmaxf(b2.y, b3.y));
    cmxv[2] = fmaxf(fmaxf(b0.z, b1.z), fmaxf(b2.z, b3.z));
    cmxv[3] = fmaxf(fmaxf(b0.w, b1.w), fmaxf(b2.w, b3.w));

    // per-thread quantization constants (4 IEEE divs per thread)
    float scale7[4], nm7[4], q14[4], halfmn[4];
    #pragma unroll
    for (int q = 0; q < 4; q++) {
        float cmn = cmnv[q];
        float crg = fmaxf(cmxv[q] - cmn, 1e-8f);
        scale7[q] = 7.0f / crg;            // (p-mn)*scale7 == norm*7
        nm7[q]    = -cmn * scale7[q];      // norm7 = fma(p, scale7, nm7)
        q14[q]    = crg / 14.0f;           // 0.5 * (crg/7)
        halfmn[q] = 0.5f * cmn;
    }

    // ---- pass 2: quantize + residual correction, write out ----
    // corrected = dq + 0.5*(p-dq) = fma(qv, crg/14, fma(0.5, p, 0.5*mn))
    float* op = out + base;
    #pragma unroll
    for (int i = 0; i < RPW; i++) {
        const int off = (w + 4 * i) * NDIM + 4 * l;
        float4 p = *(const float4*)&s_tile[off];
        float pv[4] = {p.x, p.y, p.z, p.w};
        float res[4];
        #pragma unroll
        for (int q = 0; q < 4; q++) {
            float norm7 = fmaf(pv[q], scale7[q], nm7[q]);  // in [0,7] by construction
            float qv    = rintf(norm7);                    // half-to-even
            res[q] = fmaf(qv, q14[q], fmaf(0.5f, pv[q], halfmn[q]));
        }
        *(float4*)(op + (size_t)off) = make_float4(res[0], res[1], res[2], res[3]);
    }
}

static void build_lut_host(LutParams* p) {
    const double PHI = 1.6180339887498948482045868343656;
    const double GA  = 6.2831853071795864769252867665590 / (PHI * PHI);
    for (int k = 0; k < 64; k++) {
        double a1 = GA * (double)(k + 1);
        p->v[k]        = (float)cos(a1);
        p->v[64 + k]   = (float)sin(a1);
        if (k < 63) {
            double a2 = GA * (double)(k + 1) * PHI;
            p->v[128 + k] = (float)cos(a2);
            p->v[192 + k] = (float)sin(a2);
        } else {
            p->v[128 + k] = 0.0f;
            p->v[192 + k] = 0.0f;
        }
        int kk = (k < 32) ? k : (k + 32);   // layer3 accepted ks: 0..31, 64..95
        double a3 = GA * (double)(kk + 1) * PHI * PHI;
        p->v[256 + k] = (float)cos(a3);
        p->v[320 + k] = (float)sin(a3);
    }
}

extern "C" void kernel_launch(void* const* d_in, const int* in_sizes, int n_in,
                              void* d_out, int out_size) {
    const float* x = (const float*)d_in[0];
    float* out = (float*)d_out;
    int nrows  = in_sizes[0] / NDIM;
    int ntiles = nrows / TROWS;
    LutParams lp;
    build_lut_host(&lp);                 // host-side, no device work
    nautilus_main<<<ntiles, NTHREADS>>>(x, out, lp);
}

// round 16
// speedup vs baseline: 1.3610x; 1.0440x over previous
#include <cuda_runtime.h>
#include <cuda_pipeline.h>
#include <math.h>
#include <stdint.h>

#define NDIM     128
#define TROWS    60
#define NWARPS   4
#define RPW      15      // rows per warp
#define PDEPTH   8       // cp.async software-pipeline depth
#define NTHREADS 128
#define FULLMASK 0xFFFFFFFFu

// LUT layout: c1[0:64) s1[64:128) c2[128:192) s2[192:256) c3[256:320) s3[320:384)
struct LutParams { float v[384]; };

// Degree-15 odd minimax atan on [0,1] + octant fixup; abs err ~1e-6.
__device__ __forceinline__ float fast_atan2f(float y, float x) {
    float ax = fabsf(x), ay = fabsf(y);
    float mx = fmaxf(ax, ay), mn = fminf(ax, ay);
    float t  = __fdividef(mn, mx);
    float t2 = t * t;
    float p  = -0.0040540580f;
    p = fmaf(p, t2,  0.0218612288f);
    p = fmaf(p, t2, -0.0559098861f);
    p = fmaf(p, t2,  0.0964200441f);
    p = fmaf(p, t2, -0.1390853351f);
    p = fmaf(p, t2,  0.1994653599f);
    p = fmaf(p, t2, -0.3332985605f);
    p = fmaf(p, t2,  0.9999993329f);
    float a = p * t;
    if (ay > ax)   a = 1.57079632679489662f - a;
    if (x < 0.0f)  a = 3.14159265358979323f - a;
    return copysignf(a, y);
}

// branchless fast sqrt: h * rsqrt(max(h, tiny)); h==0 -> 0 * finite = 0
__device__ __forceinline__ float fast_sqrtf(float h) {
    return h * rsqrtf(fmaxf(h, 1e-38f));
}

__global__ __launch_bounds__(NTHREADS, 6)
void nautilus_main(const float* __restrict__ x, float* __restrict__ out,
                   const LutParams lp) {
    __shared__ float s_lut[384];
    __shared__ float s_tile[TROWS * NDIM];       // 30720 B; slots are THREAD-PRIVATE
    __shared__ float s_pmin[NWARPS][NDIM];       // per-warp partial min
    __shared__ float s_pmax[NWARPS][NDIM];

    const int tid = threadIdx.x;
    const int w   = tid >> 5;
    const int l   = tid & 31;
    const size_t base = (size_t)blockIdx.x * (size_t)(TROWS * NDIM);

    // ---- prologue: issue first PDEPTH row-slice copies (bounded MLP) ----
    #pragma unroll
    for (int i = 0; i < PDEPTH; i++) {
        const int off = (w + 4 * i) * NDIM + 4 * l;
        __pipeline_memcpy_async(&s_tile[off], x + base + off, 16);
        __pipeline_commit();
    }

    // stage LUT param -> smem (uniform LDC; overlaps with cp.async flight)
    #pragma unroll
    for (int i = tid; i < 384; i += NTHREADS) s_lut[i] = lp.v[i];
    __syncthreads();

    // ---- per-thread rotation constants (uniform across rows) ----
    float c1a = s_lut[2 * l],       s1a = s_lut[64 + 2 * l];
    float c1b = s_lut[2 * l + 1],   s1b = s_lut[64 + 2 * l + 1];
    float cwi = s_lut[128 + 2 * l], swi = s_lut[192 + 2 * l];      // L2 within: k=2l
    // L2 cross coefficients; edge lanes get identity so no predication is needed
    float crr = (l < 31) ? s_lut[128 + 2 * l + 1] : 1.0f;
    float srr = (l < 31) ? s_lut[192 + 2 * l + 1] : 0.0f;
    float cll = (l > 0)  ? s_lut[128 + 2 * l - 1] : 1.0f;
    float sll = (l > 0)  ? s_lut[192 + 2 * l - 1] : 0.0f;
    const bool iside = ((l & 8) == 0);
    int ilane = l & ~8;                                             // i-side lane of xor-8 pair
    float c3v[4], s3v[4];
    #pragma unroll
    for (int q = 0; q < 4; q++) {
        int e = 4 * ilane + q;                 // i-side element index
        int m = (e >= 64) ? (e - 32) : e;      // LUT slot
        c3v[q] = s_lut[256 + m];
        float s3 = s_lut[320 + m];
        s3v[q] = iside ? -s3 : s3;             // i-side: v*c - p*s ; j-side: v*c + p*s
    }

    float mn0 =  INFINITY, mn1 =  INFINITY, mn2 =  INFINITY, mn3 =  INFINITY;
    float mx0 = -INFINITY, mx1 = -INFINITY, mx2 = -INFINITY, mx3 = -INFINITY;

    // one row's full chain: rotate -> polar -> min/max -> write back
    auto process_row = [&](int i) {
        const int off = (w + 4 * i) * NDIM + 4 * l;
        float4 v = *(const float4*)&s_tile[off];
        float v0 = v.x, v1 = v.y, v2 = v.z, v3 = v.w;
        float a, b;

        // layer 1: (2k, 2k+1)
        a = v0; b = v1; v0 = a * c1a - b * s1a; v1 = a * s1a + b * c1a;
        a = v2; b = v3; v2 = a * c1b - b * s1b; v3 = a * s1b + b * c1b;

        // layer 2 within-thread: (4l+1, 4l+2), k=2l
        a = v1; b = v2; v1 = a * cwi - b * swi; v2 = a * swi + b * cwi;

        // layer 2 cross-thread: (4l+3, 4l+4), k=2l+1 — branchless (edge coeffs = identity)
        float nb = __shfl_down_sync(FULLMASK, v0, 1);
        float na = __shfl_up_sync(FULLMASK, v3, 1);
        v3 = v3 * crr - nb * srr;
        v0 = na * sll + v0 * cll;

        // layer 3: (k, k+32) via shfl.xor 8, branch-free (sign folded into s3v)
        float p0 = __shfl_xor_sync(FULLMASK, v0, 8);
        float p1 = __shfl_xor_sync(FULLMASK, v1, 8);
        float p2 = __shfl_xor_sync(FULLMASK, v2, 8);
        float p3 = __shfl_xor_sync(FULLMASK, v3, 8);
        v0 = fmaf(p0, s3v[0], v0 * c3v[0]);
        v1 = fmaf(p1, s3v[1], v1 * c3v[1]);
        v2 = fmaf(p2, s3v[2], v2 * c3v[2]);
        v3 = fmaf(p3, s3v[3], v3 * c3v[3]);

        // polar: (even, odd) pairs are intra-thread
        float h0  = fmaf(v0, v0, v1 * v1);
        float h1  = fmaf(v2, v2, v3 * v3);
        float r0  = fast_sqrtf(h0);
        float r1  = fast_sqrtf(h1);
        float th0 = fast_atan2f(v1, v0);
        float th1 = fast_atan2f(v3, v2);

        mn0 = fminf(mn0, r0);  mx0 = fmaxf(mx0, r0);
        mn1 = fminf(mn1, th0); mx1 = fmaxf(mx1, th0);
        mn2 = fminf(mn2, r1);  mx2 = fmaxf(mx2, r1);
        mn3 = fminf(mn3, th1); mx3 = fmaxf(mx3, th1);

        *(float4*)&s_tile[off] = make_float4(r0, th0, r1, th1);
    };

    // ---- pass 1: 7 row-pairs + tail, ONE wait per pair (two chains interleave) ----
    #pragma unroll
    for (int j = 0; j < 7; j++) {
        const int i0 = 2 * j, i1 = 2 * j + 1;
        // look-ahead copies for rows i0+PDEPTH, i1+PDEPTH
        if (i0 + PDEPTH < RPW) {
            const int foff = (w + 4 * (i0 + PDEPTH)) * NDIM + 4 * l;
            __pipeline_memcpy_async(&s_tile[foff], x + base + foff, 16);
            __pipeline_commit();
        }
        if (i1 + PDEPTH < RPW) {
            const int foff = (w + 4 * (i1 + PDEPTH)) * NDIM + 4 * l;
            __pipeline_memcpy_async(&s_tile[foff], x + base + foff, 16);
            __pipeline_commit();
        }
        // total commits so far = min(8 + 2(j+1), 15); need groups 0..i1 done
        const int commits = (8 + 2 * (j + 1) < RPW) ? (8 + 2 * (j + 1)) : RPW;
        __pipeline_wait_prior(commits - (i1 + 1));
        process_row(i0);
        process_row(i1);
    }
    __pipeline_wait_prior(0);
    process_row(14);

    *(float4*)&s_pmin[w][4 * l] = make_float4(mn0, mn1, mn2, mn3);
    *(float4*)&s_pmax[w][4 * l] = make_float4(mx0, mx1, mx2, mx3);
    __syncthreads();

    // single-barrier reduction: every thread combines the 4 warp partials
    float4 a0 = *(const float4*)&s_pmin[0][4 * l];
    float4 a1 = *(const float4*)&s_pmin[1][4 * l];
    float4 a2 = *(const float4*)&s_pmin[2][4 * l];
    float4 a3 = *(const float4*)&s_pmin[3][4 * l];
    float4 b0 = *(const float4*)&s_pmax[0][4 * l];
    float4 b1 = *(const float4*)&s_pmax[1][4 * l];
    float4 b2 = *(const float4*)&s_pmax[2][4 * l];
    float4 b3 = *(const float4*)&s_pmax[3][4 * l];
    float cmnv[4], cmxv[4];
    cmnv[0] = fminf(fminf(a0.x, a1.x), fminf(a2.x, a3.x));
    cmnv[1] = fminf(fminf(a0.y, a1.y), fminf(a2.y, a3.y));
    cmnv[2] = fminf(fminf(a0.z, a1.z), fminf(a2.z, a3.z));
    cmnv[3] = fminf(fminf(a0.w, a1.w), fminf(a2.w, a3.w));
    cmxv[0] = fmaxf(fmaxf(b0.x, b1.x), fmaxf(b2.x, b3.x));
    cmxv[1] = fmaxf(fmaxf(b0.y, b1.y), fmaxf(b2.y, b3.y));
    cmxv[2] = fmaxf(fmaxf(b0.z, b1.z), fmaxf(b2.z, b3.z));
    cmxv[3] = fmaxf(fmaxf(b0.w, b1.w), fmaxf(b2.w, b3.w));

    // per-thread quantization constants (4 IEEE divs per thread)
    float scale7[4], nm7[4], q14[4], halfmn[4];
    #pragma unroll
    for (int q = 0; q < 4; q++) {
        float cmn = cmnv[q];
        float crg = fmaxf(cmxv[q] - cmn, 1e-8f);
        scale7[q] = 7.0f / crg;            // (p-mn)*scale7 == norm*7
        nm7[q]    = -cmn * scale7[q];      // norm7 = fma(p, scale7, nm7)
        q14[q]    = crg / 14.0f;           // 0.5 * (crg/7)
        halfmn[q] = 0.5f * cmn;
    }

    // ---- pass 2: quantize + residual correction, write out ----
    // corrected = dq + 0.5*(p-dq) = fma(qv, crg/14, fma(0.5, p, 0.5*mn))
    float* op = out + base;
    #pragma unroll
    for (int i = 0; i < RPW; i++) {
        const int off = (w + 4 * i) * NDIM + 4 * l;
        float4 p = *(const float4*)&s_tile[off];
        float pv[4] = {p.x, p.y, p.z, p.w};
        float res[4];
        #pragma unroll
        for (int q = 0; q < 4; q++) {
            float norm7 = fmaf(pv[q], scale7[q], nm7[q]);  // in [0,7] by construction
            float qv    = rintf(norm7);                    // half-to-even
            res[q] = fmaf(qv, q14[q], fmaf(0.5f, pv[q], halfmn[q]));
        }
        *(float4*)(op + (size_t)off) = make_float4(res[0], res[1], res[2], res[3]);
    }
}

static void build_lut_host(LutParams* p) {
    const double PHI = 1.6180339887498948482045868343656;
    const double GA  = 6.2831853071795864769252867665590 / (PHI * PHI);
    for (int k = 0; k < 64; k++) {
        double a1 = GA * (double)(k + 1);
        p->v[k]        = (float)cos(a1);
        p->v[64 + k]   = (float)sin(a1);
        if (k < 63) {
            double a2 = GA * (double)(k + 1) * PHI;
            p->v[128 + k] = (float)cos(a2);
            p->v[192 + k] = (float)sin(a2);
        } else {
            p->v[128 + k] = 0.0f;
            p->v[192 + k] = 0.0f;
        }
        int kk = (k < 32) ? k : (k + 32);   // layer3 accepted ks: 0..31, 64..95
        double a3 = GA * (double)(kk + 1) * PHI * PHI;
        p->v[256 + k] = (float)cos(a3);
        p->v[320 + k] = (float)sin(a3);
    }
}

extern "C" void kernel_launch(void* const* d_in, const int* in_sizes, int n_in,
                              void* d_out, int out_size) {
    const float* x = (const float*)d_in[0];
    float* out = (float*)d_out;
    int nrows  = in_sizes[0] / NDIM;
    int ntiles = nrows / TROWS;
    LutParams lp;
    build_lut_host(&lp);                 // host-side, no device work
    nautilus_main<<<ntiles, NTHREADS>>>(x, out, lp);
}

// round 17
// speedup vs baseline: 1.3620x; 1.0007x over previous
#include <cuda_runtime.h>
#include <cuda_pipeline.h>
#include <math.h>
#include <stdint.h>

#define NDIM     128
#define TROWS    60
#define NWARPS   4
#define RPW      15      // rows per warp
#define PDEPTH   8       // cp.async software-pipeline depth
#define NTHREADS 128
#define FULLMASK 0xFFFFFFFFu

// LUT layout: c1[0:64) s1[64:128) c2[128:192) s2[192:256) c3[256:320) s3[320:384)
struct LutParams { float v[384]; };

// Degree-15 odd minimax atan on [0,1] + octant fixup; abs err ~1e-6.
__device__ __forceinline__ float fast_atan2f(float y, float x) {
    float ax = fabsf(x), ay = fabsf(y);
    float mx = fmaxf(ax, ay), mn = fminf(ax, ay);
    float t  = __fdividef(mn, mx);
    float t2 = t * t;
    float p  = -0.0040540580f;
    p = fmaf(p, t2,  0.0218612288f);
    p = fmaf(p, t2, -0.0559098861f);
    p = fmaf(p, t2,  0.0964200441f);
    p = fmaf(p, t2, -0.1390853351f);
    p = fmaf(p, t2,  0.1994653599f);
    p = fmaf(p, t2, -0.3332985605f);
    p = fmaf(p, t2,  0.9999993329f);
    float a = p * t;
    if (ay > ax)   a = 1.57079632679489662f - a;
    if (x < 0.0f)  a = 3.14159265358979323f - a;
    return copysignf(a, y);
}

// branchless fast sqrt: h * rsqrt(max(h, tiny)); h==0 -> 0 * finite = 0
__device__ __forceinline__ float fast_sqrtf(float h) {
    return h * rsqrtf(fmaxf(h, 1e-38f));
}

__global__ __launch_bounds__(NTHREADS, 6)
void nautilus_main(const float* __restrict__ x, float* __restrict__ out,
                   const LutParams lp) {
    __shared__ float s_lut[384];
    __shared__ float s_tile[TROWS * NDIM];       // 30720 B; slots are THREAD-PRIVATE
    __shared__ float s_pmin[NWARPS][NDIM];       // per-warp partial min
    __shared__ float s_pmax[NWARPS][NDIM];

    const int tid = threadIdx.x;
    const int w   = tid >> 5;
    const int l   = tid & 31;
    const size_t base = (size_t)blockIdx.x * (size_t)(TROWS * NDIM);

    // ---- prologue: issue first PDEPTH row-slice copies (bounded MLP) ----
    #pragma unroll
    for (int i = 0; i < PDEPTH; i++) {
        const int off = (w + 4 * i) * NDIM + 4 * l;
        __pipeline_memcpy_async(&s_tile[off], x + base + off, 16);
        __pipeline_commit();
    }

    // stage LUT param -> smem (uniform LDC; overlaps with cp.async flight)
    #pragma unroll
    for (int i = tid; i < 384; i += NTHREADS) s_lut[i] = lp.v[i];
    __syncthreads();

    // ---- per-thread rotation constants (uniform across rows) ----
    float c1a = s_lut[2 * l],       s1a = s_lut[64 + 2 * l];
    float c1b = s_lut[2 * l + 1],   s1b = s_lut[64 + 2 * l + 1];
    float cwi = s_lut[128 + 2 * l], swi = s_lut[192 + 2 * l];      // L2 within: k=2l
    // L2 cross coefficients; edge lanes get identity so no predication is needed
    float crr = (l < 31) ? s_lut[128 + 2 * l + 1] : 1.0f;
    float srr = (l < 31) ? s_lut[192 + 2 * l + 1] : 0.0f;
    float cll = (l > 0)  ? s_lut[128 + 2 * l - 1] : 1.0f;
    float sll = (l > 0)  ? s_lut[192 + 2 * l - 1] : 0.0f;
    const bool iside = ((l & 8) == 0);
    int ilane = l & ~8;                                             // i-side lane of xor-8 pair
    float c3v[4], s3v[4];
    #pragma unroll
    for (int q = 0; q < 4; q++) {
        int e = 4 * ilane + q;                 // i-side element index
        int m = (e >= 64) ? (e - 32) : e;      // LUT slot
        c3v[q] = s_lut[256 + m];
        float s3 = s_lut[320 + m];
        s3v[q] = iside ? -s3 : s3;             // i-side: v*c - p*s ; j-side: v*c + p*s
    }

    float mn0 =  INFINITY, mn1 =  INFINITY, mn2 =  INFINITY, mn3 =  INFINITY;
    float mx0 = -INFINITY, mx1 = -INFINITY, mx2 = -INFINITY, mx3 = -INFINITY;

    // one row's full chain: rotate -> polar -> min/max -> write back
    auto process_row = [&](int i) {
        const int off = (w + 4 * i) * NDIM + 4 * l;
        float4 v = *(const float4*)&s_tile[off];
        float v0 = v.x, v1 = v.y, v2 = v.z, v3 = v.w;
        float a, b;

        // layer 1: (2k, 2k+1)
        a = v0; b = v1; v0 = a * c1a - b * s1a; v1 = a * s1a + b * c1a;
        a = v2; b = v3; v2 = a * c1b - b * s1b; v3 = a * s1b + b * c1b;

        // layer 2 within-thread: (4l+1, 4l+2), k=2l
        a = v1; b = v2; v1 = a * cwi - b * swi; v2 = a * swi + b * cwi;

        // layer 2 cross-thread: (4l+3, 4l+4), k=2l+1 — branchless (edge coeffs = identity)
        float nb = __shfl_down_sync(FULLMASK, v0, 1);
        float na = __shfl_up_sync(FULLMASK, v3, 1);
        v3 = v3 * crr - nb * srr;
        v0 = na * sll + v0 * cll;

        // layer 3: (k, k+32) via shfl.xor 8, branch-free (sign folded into s3v)
        float p0 = __shfl_xor_sync(FULLMASK, v0, 8);
        float p1 = __shfl_xor_sync(FULLMASK, v1, 8);
        float p2 = __shfl_xor_sync(FULLMASK, v2, 8);
        float p3 = __shfl_xor_sync(FULLMASK, v3, 8);
        v0 = fmaf(p0, s3v[0], v0 * c3v[0]);
        v1 = fmaf(p1, s3v[1], v1 * c3v[1]);
        v2 = fmaf(p2, s3v[2], v2 * c3v[2]);
        v3 = fmaf(p3, s3v[3], v3 * c3v[3]);

        // polar: (even, odd) pairs are intra-thread
        float h0  = fmaf(v0, v0, v1 * v1);
        float h1  = fmaf(v2, v2, v3 * v3);
        float r0  = fast_sqrtf(h0);
        float r1  = fast_sqrtf(h1);
        float th0 = fast_atan2f(v1, v0);
        float th1 = fast_atan2f(v3, v2);

        mn0 = fminf(mn0, r0);  mx0 = fmaxf(mx0, r0);
        mn1 = fminf(mn1, th0); mx1 = fmaxf(mx1, th0);
        mn2 = fminf(mn2, r1);  mx2 = fmaxf(mx2, r1);
        mn3 = fminf(mn3, th1); mx3 = fmaxf(mx3, th1);

        *(float4*)&s_tile[off] = make_float4(r0, th0, r1, th1);
    };

    // ---- pass 1: 5 groups x 3 rows, ONE wait per group (three chains interleave) ----
    #pragma unroll
    for (int j = 0; j < 5; j++) {
        const int i0 = 3 * j, i1 = 3 * j + 1, i2 = 3 * j + 2;
        // look-ahead copies for rows i0+8, i1+8, i2+8 (when in range)
        #pragma unroll
        for (int q = 0; q < 3; q++) {
            const int fr = 3 * j + q + PDEPTH;
            if (fr < RPW) {
                const int foff = (w + 4 * fr) * NDIM + 4 * l;
                __pipeline_memcpy_async(&s_tile[foff], x + base + foff, 16);
                __pipeline_commit();
            }
        }
        // commits so far = min(8 + 3(j+1), 15); need groups 0..i2 done
        const int commits = (8 + 3 * (j + 1) < RPW) ? (8 + 3 * (j + 1)) : RPW;
        __pipeline_wait_prior(commits - (i2 + 1));
        process_row(i0);
        process_row(i1);
        process_row(i2);
    }

    *(float4*)&s_pmin[w][4 * l] = make_float4(mn0, mn1, mn2, mn3);
    *(float4*)&s_pmax[w][4 * l] = make_float4(mx0, mx1, mx2, mx3);
    __syncthreads();

    // single-barrier reduction: every thread combines the 4 warp partials
    float4 a0 = *(const float4*)&s_pmin[0][4 * l];
    float4 a1 = *(const float4*)&s_pmin[1][4 * l];
    float4 a2 = *(const float4*)&s_pmin[2][4 * l];
    float4 a3 = *(const float4*)&s_pmin[3][4 * l];
    float4 b0 = *(const float4*)&s_pmax[0][4 * l];
    float4 b1 = *(const float4*)&s_pmax[1][4 * l];
    float4 b2 = *(const float4*)&s_pmax[2][4 * l];
    float4 b3 = *(const float4*)&s_pmax[3][4 * l];
    float cmnv[4], cmxv[4];
    cmnv[0] = fminf(fminf(a0.x, a1.x), fminf(a2.x, a3.x));
    cmnv[1] = fminf(fminf(a0.y, a1.y), fminf(a2.y, a3.y));
    cmnv[2] = fminf(fminf(a0.z, a1.z), fminf(a2.z, a3.z));
    cmnv[3] = fminf(fminf(a0.w, a1.w), fminf(a2.w, a3.w));
    cmxv[0] = fmaxf(fmaxf(b0.x, b1.x), fmaxf(b2.x, b3.x));
    cmxv[1] = fmaxf(fmaxf(b0.y, b1.y), fmaxf(b2.y, b3.y));
    cmxv[2] = fmaxf(fmaxf(b0.z, b1.z), fmaxf(b2.z, b3.z));
    cmxv[3] = fmaxf(fmaxf(b0.w, b1.w), fmaxf(b2.w, b3.w));

    // per-thread quantization constants (4 IEEE divs per thread)
    float scale7[4], nm7[4], q14[4], halfmn[4];
    #pragma unroll
    for (int q = 0; q < 4; q++) {
        float cmn = cmnv[q];
        float crg = fmaxf(cmxv[q] - cmn, 1e-8f);
        scale7[q] = 7.0f / crg;            // (p-mn)*scale7 == norm*7
        nm7[q]    = -cmn * scale7[q];      // norm7 = fma(p, scale7, nm7)
        q14[q]    = crg / 14.0f;           // 0.5 * (crg/7)
        halfmn[q] = 0.5f * cmn;
    }

    // ---- pass 2: quantize + residual correction, write out ----
    // corrected = dq + 0.5*(p-dq) = fma(qv, crg/14, fma(0.5, p, 0.5*mn))
    float* op = out + base;
    #pragma unroll
    for (int i = 0; i < RPW; i++) {
        const int off = (w + 4 * i) * NDIM + 4 * l;
        float4 p = *(const float4*)&s_tile[off];
        float pv[4] = {p.x, p.y, p.z, p.w};
        float res[4];
        #pragma unroll
        for (int q = 0; q < 4; q++) {
            float norm7 = fmaf(pv[q], scale7[q], nm7[q]);  // in [0,7] by construction
            float qv    = rintf(norm7);                    // half-to-even
            res[q] = fmaf(qv, q14[q], fmaf(0.5f, pv[q], halfmn[q]));
        }
        *(float4*)(op + (size_t)off) = make_float4(res[0], res[1], res[2], res[3]);
    }
}

static void build_lut_host(LutParams* p) {
    const double PHI = 1.6180339887498948482045868343656;
    const double GA  = 6.2831853071795864769252867665590 / (PHI * PHI);
    for (int k = 0; k < 64; k++) {
        double a1 = GA * (double)(k + 1);
        p->v[k]        = (float)cos(a1);
        p->v[64 + k]   = (float)sin(a1);
        if (k < 63) {
            double a2 = GA * (double)(k + 1) * PHI;
            p->v[128 + k] = (float)cos(a2);
            p->v[192 + k] = (float)sin(a2);
        } else {
            p->v[128 + k] = 0.0f;
            p->v[192 + k] = 0.0f;
        }
        int kk = (k < 32) ? k : (k + 32);   // layer3 accepted ks: 0..31, 64..95
        double a3 = GA * (double)(kk + 1) * PHI * PHI;
        p->v[256 + k] = (float)cos(a3);
        p->v[320 + k] = (float)sin(a3);
    }
}

extern "C" void kernel_launch(void* const* d_in, const int* in_sizes, int n_in,
                              void* d_out, int out_size) {
    const float* x = (const float*)d_in[0];
    float* out = (float*)d_out;
    int nrows  = in_sizes[0] / NDIM;
    int ntiles = nrows / TROWS;
    LutParams lp;
    build_lut_host(&lp);                 // host-side, no device work
    nautilus_main<<<ntiles, NTHREADS>>>(x, out, lp);
}